// round 2
// baseline (speedup 1.0000x reference)
#include <cuda_runtime.h>

#define NBOX   2000
#define SORTN  2048
#define MAXDET 10
#define TOPK   5
#define IMG_H  512
#define IMG_W  512
#define NIMG   16
#define CONF_T 0.2f
#define IOU_T  0.4f
#define T1     1024

// scratch for rects: per image, per slot: {valid, x1, y1, x2, y2}
__device__ int g_rect[NIMG * MAXDET * 5];

__global__ __launch_bounds__(T1)
void stage1_kernel(const float* __restrict__ region,
                   const float* __restrict__ neg,
                   float* __restrict__ out_tbox,
                   float* __restrict__ out_keep2)
{
    extern __shared__ unsigned char smem[];
    unsigned long long* key = (unsigned long long*)smem;           // SORTN u64
    float* bx1 = (float*)(key + SORTN);                             // NBOX
    float* by1 = bx1 + NBOX;
    float* bx2 = by1 + NBOX;
    float* by2 = bx2 + NBOX;
    unsigned char* keep = (unsigned char*)(by2 + NBOX);             // NBOX

    __shared__ int s_hasconf, s_cnt, s_stop, s_slots[MAXDET];

    const int b   = blockIdx.x;
    const int tid = threadIdx.x;
    if (tid == 0) { s_hasconf = 0; s_cnt = 0; s_stop = 0; }
    __syncthreads();

    // ---- load boxes, build sort keys: (score_bits << 32) | (~idx) ----
    const float* rb = region + (long)b * NBOX * 5;
    for (int i = tid; i < NBOX; i += T1) {
        float x1 = rb[i*5+0], y1 = rb[i*5+1];
        float x2 = rb[i*5+2], y2 = rb[i*5+3];
        float cf = rb[i*5+4];
        bx1[i] = x1; by1[i] = y1; bx2[i] = x2; by2[i] = y2;
        key[i] = ((unsigned long long)__float_as_uint(cf) << 32)
               | (unsigned long long)(0xFFFFFFFFu - (unsigned)i);
        if (cf > CONF_T) s_hasconf = 1;
    }
    for (int i = NBOX + tid; i < SORTN; i += T1) key[i] = 0ULL;
    __syncthreads();

    // ---- bitonic sort, descending (== stable argsort of -score) ----
    for (int k = 2; k <= SORTN; k <<= 1) {
        for (int j = k >> 1; j > 0; j >>= 1) {
            for (int i = tid; i < SORTN; i += T1) {
                int ixj = i ^ j;
                if (ixj > i) {
                    unsigned long long a = key[i], c = key[ixj];
                    bool up = ((i & k) == 0);
                    if (up ? (a < c) : (a > c)) { key[i] = c; key[ixj] = a; }
                }
            }
            __syncthreads();
        }
    }

    const bool  hasconf = (s_hasconf != 0);
    const int   cap  = hasconf ? MAXDET : TOPK;
    const float thr0 = hasconf ? CONF_T : 0.0f;

    // ---- init keep from sorted conf (key high bits) ----
    for (int i = tid; i < NBOX; i += T1) {
        float cf = __uint_as_float((unsigned)(key[i] >> 32));
        keep[i] = (cf > thr0) ? (unsigned char)1 : (unsigned char)0;
    }
    __syncthreads();

    // ---- greedy NMS with early exit once `cap` kept & tiny-pass boxes found ----
    for (int i = 0; i < NBOX; i++) {
        if (keep[i]) {
            int oi = (int)(0xFFFFFFFFu - (unsigned)(key[i] & 0xFFFFFFFFull));
            float x1i = bx1[oi], y1i = by1[oi], x2i = bx2[oi], y2i = by2[oi];
            if (tid == 0) {
                if (x2i - x1i >= 1.0f && y2i - y1i >= 1.0f) {
                    s_slots[s_cnt] = i;
                    s_cnt++;
                    if (s_cnt >= cap) s_stop = 1;
                }
            }
            float ai = fmaxf(x2i - x1i, 0.0f) * fmaxf(y2i - y1i, 0.0f);
            for (int jj = i + 1 + tid; jj < NBOX; jj += T1) {
                if (!keep[jj]) continue;
                int oj = (int)(0xFFFFFFFFu - (unsigned)(key[jj] & 0xFFFFFFFFull));
                float x1j = bx1[oj], y1j = by1[oj], x2j = bx2[oj], y2j = by2[oj];
                float aj  = fmaxf(x2j - x1j, 0.0f) * fmaxf(y2j - y1j, 0.0f);
                float ix1 = fmaxf(x1i, x1j), iy1 = fmaxf(y1i, y1j);
                float ix2 = fminf(x2i, x2j), iy2 = fminf(y2i, y2j);
                float inter = fmaxf(ix2 - ix1, 0.0f) * fmaxf(iy2 - iy1, 0.0f);
                float iou = inter / (ai + aj - inter + 1e-9f);
                if (iou > IOU_T) keep[jj] = 0;
            }
        }
        __syncthreads();
        if (s_stop) break;
    }

    // ---- tiny epilogue: 10-box combine, stable sort, NMS, outputs ----
    if (tid == 0) {
        const float* nb = neg + (long)b * MAXDET * 5;
        float tmp[MAXDET][5];
        int cnt = s_cnt;
        for (int s = 0; s < MAXDET; s++) {
            if (s < cnt) {
                int i  = s_slots[s];
                int oi = (int)(0xFFFFFFFFu - (unsigned)(key[i] & 0xFFFFFFFFull));
                tmp[s][0] = bx1[oi]; tmp[s][1] = by1[oi];
                tmp[s][2] = bx2[oi]; tmp[s][3] = by2[oi];
                tmp[s][4] = __uint_as_float((unsigned)(key[i] >> 32));
            } else {
                for (int f = 0; f < 5; f++) tmp[s][f] = nb[s*5+f];
            }
        }
        // stable insertion sort, descending conf
        int ord[MAXDET];
        for (int s = 0; s < MAXDET; s++) ord[s] = s;
        for (int a = 1; a < MAXDET; a++) {
            int v = ord[a]; float cv = tmp[v][4];
            int c = a - 1;
            while (c >= 0 && tmp[ord[c]][4] < cv) { ord[c+1] = ord[c]; c--; }
            ord[c+1] = v;
        }
        float cbx[MAXDET][5];
        for (int s = 0; s < MAXDET; s++)
            for (int f = 0; f < 5; f++) cbx[s][f] = tmp[ord[s]][f];

        int k2[MAXDET];
        for (int s = 0; s < MAXDET; s++) k2[s] = (cbx[s][4] > 0.0f) ? 1 : 0;
        for (int i2 = 0; i2 < MAXDET; i2++) {
            if (!k2[i2]) continue;
            float ai = fmaxf(cbx[i2][2]-cbx[i2][0],0.f) * fmaxf(cbx[i2][3]-cbx[i2][1],0.f);
            for (int j2 = i2 + 1; j2 < MAXDET; j2++) {
                if (!k2[j2]) continue;
                float aj  = fmaxf(cbx[j2][2]-cbx[j2][0],0.f) * fmaxf(cbx[j2][3]-cbx[j2][1],0.f);
                float ix1 = fmaxf(cbx[i2][0], cbx[j2][0]);
                float iy1 = fmaxf(cbx[i2][1], cbx[j2][1]);
                float ix2 = fminf(cbx[i2][2], cbx[j2][2]);
                float iy2 = fminf(cbx[i2][3], cbx[j2][3]);
                float inter = fmaxf(ix2 - ix1, 0.f) * fmaxf(iy2 - iy1, 0.f);
                float iou = inter / (ai + aj - inter + 1e-9f);
                if (iou > IOU_T) k2[j2] = 0;
            }
        }

        float* tb = out_tbox  + b * (MAXDET * 4);
        float* kk = out_keep2 + b * MAXDET;
        int*   gr = g_rect    + b * (MAXDET * 5);
        for (int s = 0; s < MAXDET; s++) {
            for (int f = 0; f < 4; f++)
                tb[s*4+f] = k2[s] ? cbx[s][f] : 0.0f;
            kk[s] = k2[s] ? 1.0f : 0.0f;
            gr[s*5+0] = k2[s];
            gr[s*5+1] = (int)floorf(cbx[s][0] + 0.5f);
            gr[s*5+2] = (int)floorf(cbx[s][1] + 0.5f);
            gr[s*5+3] = (int)floorf(cbx[s][2] + 0.5f);
            gr[s*5+4] = (int)floorf(cbx[s][3] + 0.5f);
        }
    }
}

__global__ __launch_bounds__(256)
void mask_kernel(float* __restrict__ out_mask)
{
    __shared__ int r[MAXDET * 5];
    const int b = blockIdx.y;
    if (threadIdx.x < MAXDET * 5) r[threadIdx.x] = g_rect[b * MAXDET * 5 + threadIdx.x];
    __syncthreads();

    int t   = blockIdx.x * blockDim.x + threadIdx.x;  // float4 index within image
    int pix = t * 4;
    int y   = pix >> 9;           // IMG_W = 512
    int x0  = pix & (IMG_W - 1);

    float m0 = 1.f, m1 = 1.f, m2 = 1.f, m3 = 1.f;
    #pragma unroll
    for (int s = 0; s < MAXDET; s++) {
        int valid = r[s*5+0];
        int rx1 = r[s*5+1], ry1 = r[s*5+2], rx2 = r[s*5+3], ry2 = r[s*5+4];
        if (valid && y >= ry1 && y < ry2) {
            if (x0     >= rx1 && x0     < rx2) m0 = 0.f;
            if (x0 + 1 >= rx1 && x0 + 1 < rx2) m1 = 0.f;
            if (x0 + 2 >= rx1 && x0 + 2 < rx2) m2 = 0.f;
            if (x0 + 3 >= rx1 && x0 + 3 < rx2) m3 = 0.f;
        }
    }
    ((float4*)out_mask)[(long)b * (IMG_H * IMG_W / 4) + t] = make_float4(m0, m1, m2, m3);
}

extern "C" void kernel_launch(void* const* d_in, const int* in_sizes, int n_in,
                              void* d_out, int out_size)
{
    // identify inputs by element count (x is unused)
    const float* region = nullptr;
    const float* neg    = nullptr;
    for (int i = 0; i < n_in; i++) {
        if (in_sizes[i] == NIMG * NBOX * 5)        region = (const float*)d_in[i];
        else if (in_sizes[i] == NIMG * MAXDET * 5) neg    = (const float*)d_in[i];
    }

    float* out      = (float*)d_out;
    float* out_mask = out;
    float* out_tbox = out + (long)NIMG * IMG_H * IMG_W;
    float* out_k2   = out_tbox + NIMG * MAXDET * 4;

    size_t smem_sz = (size_t)SORTN * 8 + 4 * (size_t)NBOX * 4 + NBOX;
    cudaFuncSetAttribute(stage1_kernel,
                         cudaFuncAttributeMaxDynamicSharedMemorySize, (int)smem_sz);

    stage1_kernel<<<NIMG, T1, smem_sz>>>(region, neg, out_tbox, out_k2);
    mask_kernel<<<dim3(IMG_H * IMG_W / 4 / 256, NIMG), 256>>>(out_mask);
}